// round 1
// baseline (speedup 1.0000x reference)
#include <cuda_runtime.h>
#include <math.h>

#define BATCH 16
#define CH    64
#define NPIX  65536          // 256*256
#define NBVEC 4
#define TILE  256            // pixels per block in main pass
#define TSTR  260            // padded tile row stride (floats); 260%32=4 -> conflict-free both phases
#define MAIN_SMEM_FLOATS (CH*TSTR + TILE + CH + TILE)   // tile + simS + rawS + part
#define MAIN_SMEM_BYTES  (MAIN_SMEM_FLOATS * 4)

// Scratch (device globals; no runtime allocation allowed)
__device__ float g_score[BATCH * NPIX];   // working score buffer
__device__ float g_raw[BATCH * CH];       // selected feature vector per batch
__device__ float g_repr[BATCH * CH];      // numerator accumulators
__device__ float g_sumsim[BATCH];         // denominator accumulators

// ---------------------------------------------------------------------------
// Init: copy score_init into working buffer, zero selectedPos output section
// ---------------------------------------------------------------------------
__global__ void k_init(const float* __restrict__ score_init, float* __restrict__ pos_out) {
    int total = BATCH * NPIX;
    for (int i = blockIdx.x * blockDim.x + threadIdx.x; i < total;
         i += gridDim.x * blockDim.x) {
        g_score[i] = score_init[i];
        pos_out[i] = 0.0f;
    }
}

// ---------------------------------------------------------------------------
// Per-batch argmax (first-index tie-break, matching jnp.argmax), extract raw,
// zero the accumulators for this iteration.
// ---------------------------------------------------------------------------
__global__ void k_argmax(const float* __restrict__ x) {
    __shared__ float sv[1024];
    __shared__ int   si[1024];
    int b = blockIdx.x;
    int tid = threadIdx.x;

    const float* sc = g_score + (size_t)b * NPIX;
    float best = -1e30f;
    int   bi   = 0;
    for (int n = tid; n < NPIX; n += 1024) {
        float v = sc[n];
        if (v > best) { best = v; bi = n; }   // per-thread indices ascending -> strict > keeps lowest
    }
    sv[tid] = best; si[tid] = bi;
    __syncthreads();
    for (int s = 512; s > 0; s >>= 1) {
        if (tid < s) {
            float v2 = sv[tid + s]; int i2 = si[tid + s];
            if (v2 > sv[tid] || (v2 == sv[tid] && i2 < si[tid])) {
                sv[tid] = v2; si[tid] = i2;
            }
        }
        __syncthreads();
    }
    int ind = si[0];
    if (tid < CH) {
        g_raw[b * CH + tid]  = x[((size_t)b * CH + tid) * NPIX + ind];
        g_repr[b * CH + tid] = 0.0f;
    }
    if (tid == CH) g_sumsim[b] = 0.0f;
}

// ---------------------------------------------------------------------------
// Main pass: one 256-pixel tile per block.
//  Phase 0: float4 global -> smem tile [CH][TSTR]
//  Phase 1: per-pixel d2 vs raw, sim, write simList, update score, block-sum sim
//  Phase 2: per-(c, group) sim-weighted channel reduction, atomicAdd to g_repr
// ---------------------------------------------------------------------------
extern __shared__ float smem[];
__global__ __launch_bounds__(256) void k_main(const float* __restrict__ x,
                                              float* __restrict__ sim_out,
                                              int it) {
    float* tileS = smem;                     // CH * TSTR
    float* simS  = smem + CH * TSTR;         // TILE
    float* rawS  = simS + TILE;              // CH
    float* partS = rawS + CH;                // TILE

    int b    = blockIdx.y;
    int base = blockIdx.x * TILE;
    int tid  = threadIdx.x;

    if (tid < CH) rawS[tid] = g_raw[b * CH + tid];

    // Phase 0: vectorized load, 4096 float4 per tile, 16 per thread
    const float* xb = x + (size_t)b * CH * NPIX + base;
#pragma unroll
    for (int l = 0; l < 16; l++) {
        int q = l * 256 + tid;
        int c = q >> 6;
        int j = (q & 63) << 2;
        float4 v = *(const float4*)(xb + (size_t)c * NPIX + j);
        *(float4*)(tileS + c * TSTR + j) = v;
    }
    __syncthreads();

    // Phase 1: d2 + sim for this thread's pixel
    {
        int n = tid;
        float d2 = 0.0f;
#pragma unroll
        for (int c = 0; c < CH; c++) {
            float d = tileS[c * TSTR + n] - rawS[c];
            d2 = fmaf(d, d, d2);
        }
        float sim = expf(-sqrtf(fmaxf(d2, 1e-12f)) * 0.05f);
        simS[n] = sim;
        sim_out[((size_t)b * NBVEC + it) * NPIX + base + n] = sim;
        float* sp = g_score + (size_t)b * NPIX + base + n;
        *sp = (1.0f - sim) * (*sp);
        partS[tid] = sim;
    }
    __syncthreads();

    // block-reduce sum of sim -> atomic
    if (tid < 128) partS[tid] += partS[tid + 128];
    __syncthreads();
    if (tid < 64)  partS[tid] += partS[tid + 64];
    __syncthreads();
    if (tid < 32) {
        float s = partS[tid] + partS[tid + 32];
#pragma unroll
        for (int o = 16; o > 0; o >>= 1) s += __shfl_down_sync(0xffffffffu, s, o);
        if (tid == 0) atomicAdd(&g_sumsim[b], s);
    }
    __syncthreads();

    // Phase 2: reprVec numerator. thread = (c = tid&63, g = tid>>6), each covers 64 pixels
    {
        int c = tid & 63;
        int g = tid >> 6;
        const float* trow = tileS + c * TSTR + g * 64;
        const float* srow = simS + g * 64;
        float acc = 0.0f;
#pragma unroll
        for (int j = 0; j < 64; j += 4) {
            float4 tv = *(const float4*)(trow + j);
            float4 sv = *(const float4*)(srow + j);
            acc = fmaf(tv.x, sv.x, acc);
            acc = fmaf(tv.y, sv.y, acc);
            acc = fmaf(tv.z, sv.z, acc);
            acc = fmaf(tv.w, sv.w, acc);
        }
        partS[tid] = acc;
    }
    __syncthreads();
    if (tid < 64) {
        float s = partS[tid] + partS[tid + 64] + partS[tid + 128] + partS[tid + 192];
        atomicAdd(&g_repr[b * CH + tid], s);
    }
}

// ---------------------------------------------------------------------------
// Finalize: vecList[b, it, c] = repr / sumSim
// ---------------------------------------------------------------------------
__global__ void k_fin(float* __restrict__ vec_out, int it) {
    int b = blockIdx.x;
    int c = threadIdx.x;
    vec_out[((size_t)b * NBVEC + it) * CH + c] = g_repr[b * CH + c] / g_sumsim[b];
}

// ---------------------------------------------------------------------------
extern "C" void kernel_launch(void* const* d_in, const int* in_sizes, int n_in,
                              void* d_out, int out_size) {
    const float* x          = (const float*)d_in[0];  // [16,64,256,256] fp32
    const float* score_init = (const float*)d_in[1];  // [16,65536] fp32
    float* out = (float*)d_out;

    // Output layout: vecList [16,4,64] | simList [16,4,65536] | selectedPos [16,1,65536]
    float* vec_out = out;
    float* sim_out = out + (size_t)BATCH * NBVEC * CH;
    float* pos_out = sim_out + (size_t)BATCH * NBVEC * NPIX;

    cudaFuncSetAttribute(k_main, cudaFuncAttributeMaxDynamicSharedMemorySize,
                         MAIN_SMEM_BYTES);

    k_init<<<256, 256>>>(score_init, pos_out);
    for (int it = 0; it < NBVEC; it++) {
        k_argmax<<<BATCH, 1024>>>(x);
        k_main<<<dim3(NPIX / TILE, BATCH), 256, MAIN_SMEM_BYTES>>>(x, sim_out, it);
        k_fin<<<BATCH, CH>>>(vec_out, it);
    }
}